// round 1
// baseline (speedup 1.0000x reference)
#include <cuda_runtime.h>
#include <cstddef>

// Problem constants (fixed shapes for AttnBlock_33767032881450)
#define BATCH 8
#define CCH   512
#define HLN   2048
#define NGRP  32
#define CPG   16          // channels per group = CCH/NGRP
#define EPSV  1e-6f

// ---------------------------------------------------------------------------
// Scratch (alloc-free: __device__ globals)
// ---------------------------------------------------------------------------
__device__ float g_hn[(size_t)BATCH * CCH * HLN];   // groupnorm output
__device__ float g_q [(size_t)BATCH * CCH * HLN];
__device__ float g_k [(size_t)BATCH * CCH * HLN];
__device__ float g_v [(size_t)BATCH * CCH * HLN];
__device__ float g_h2[(size_t)BATCH * CCH * HLN];   // attention-mixed values
__device__ float g_s [(size_t)BATCH * HLN * HLN];   // scores / probabilities

// ---------------------------------------------------------------------------
// GroupNorm: one block per (group, batch). Group = 16 contiguous channels
// x 2048 positions = 32768 contiguous floats.
// ---------------------------------------------------------------------------
__global__ void gn_kernel(const float* __restrict__ x,
                          const float* __restrict__ gamma,
                          const float* __restrict__ beta) {
    const int g = blockIdx.x;
    const int b = blockIdx.y;
    const size_t base = ((size_t)b * CCH + (size_t)g * CPG) * HLN;
    const float* xp = x + base;
    const int N = CPG * HLN;   // 32768

    float s = 0.f, s2 = 0.f;
    for (int i = threadIdx.x; i < N; i += 256) {
        float v = xp[i];
        s += v; s2 += v * v;
    }
    __shared__ float sh[256], sh2[256];
    sh[threadIdx.x] = s; sh2[threadIdx.x] = s2;
    __syncthreads();
    for (int o = 128; o > 0; o >>= 1) {
        if (threadIdx.x < o) {
            sh [threadIdx.x] += sh [threadIdx.x + o];
            sh2[threadIdx.x] += sh2[threadIdx.x + o];
        }
        __syncthreads();
    }
    const float mean = sh[0] * (1.f / N);
    const float var  = sh2[0] * (1.f / N) - mean * mean;
    const float rstd = rsqrtf(var + EPSV);

    for (int i = threadIdx.x; i < N; i += 256) {
        int c = g * CPG + (i >> 11);            // i / HLN
        g_hn[base + i] = (xp[i] - mean) * rstd * gamma[c] + beta[c];
    }
}

// ---------------------------------------------------------------------------
// Shared GEMM microkernel pieces: BM=BN=64, BK=16, 256 threads, 4x4/thread.
// ---------------------------------------------------------------------------
#define GEMM_COMPUTE(As, Bs, acc, tm, tn)                                     \
    _Pragma("unroll")                                                         \
    for (int kk = 0; kk < 16; kk++) {                                         \
        float4 av = *(const float4*)&As[kk][tm * 4];                          \
        float4 bv = *(const float4*)&Bs[kk][tn * 4];                          \
        float ar4[4] = {av.x, av.y, av.z, av.w};                              \
        float br4[4] = {bv.x, bv.y, bv.z, bv.w};                              \
        _Pragma("unroll")                                                     \
        for (int ii = 0; ii < 4; ii++)                                        \
            _Pragma("unroll")                                                 \
            for (int jj = 0; jj < 4; jj++)                                    \
                acc[ii][jj] += ar4[ii] * br4[jj];                             \
    }

// conv1x1 GEMM: Y[b,o,n] = sum_c W[o,c] * X[b,c,n] + bias[o] (+ R[b,o,n])
// W: [512,512] row-major (K contiguous)  -> transpose-load into As[k][m]
// X: [C,H] per batch (n contiguous)      -> natural load into Bs[k][n]
template <bool RESID>
__global__ void conv_gemm(const float* __restrict__ W,
                          const float* __restrict__ bias,
                          const float* __restrict__ X,
                          const float* __restrict__ R,
                          float* __restrict__ Y) {
    const int b  = blockIdx.z;
    const int m0 = blockIdx.y * 64;
    const int n0 = blockIdx.x * 64;
    const float* Xb = X + (size_t)b * CCH * HLN;

    __shared__ __align__(16) float As[16][64];
    __shared__ __align__(16) float Bs[16][64];
    float acc[4][4] = {};

    const int t  = threadIdx.x;
    const int tm = t >> 4, tn = t & 15;
    const int ar = t >> 2,  ac4 = (t & 3) * 4;   // A transpose load: 64 rows x 16 cols
    const int br = t >> 4,  bc4 = (t & 15) * 4;  // B natural load:   16 rows x 64 cols

    for (int k0 = 0; k0 < CCH; k0 += 16) {
        float4 a4 = *(const float4*)&W[(size_t)(m0 + ar) * CCH + k0 + ac4];
        float4 b4 = *(const float4*)&Xb[(size_t)(k0 + br) * HLN + n0 + bc4];
        As[ac4 + 0][ar] = a4.x; As[ac4 + 1][ar] = a4.y;
        As[ac4 + 2][ar] = a4.z; As[ac4 + 3][ar] = a4.w;
        *(float4*)&Bs[br][bc4] = b4;
        __syncthreads();
        GEMM_COMPUTE(As, Bs, acc, tm, tn)
        __syncthreads();
    }

    #pragma unroll
    for (int i = 0; i < 4; i++) {
        const int o = m0 + tm * 4 + i;
        const float bi = bias[o];
        const size_t row = (size_t)b * CCH * HLN + (size_t)o * HLN + n0;
        #pragma unroll
        for (int j = 0; j < 4; j++) {
            float v = acc[i][j] + bi;
            if (RESID) v += R[row + tn * 4 + j];
            Y[row + tn * 4 + j] = v;
        }
    }
}

// scores: S[b,i,j] = scale * sum_c Q[b,c,i] * K[b,c,j]
// Both operands are [K=512, M/N=2048] layout (m/n contiguous) -> natural loads.
__global__ void score_gemm() {
    const int b  = blockIdx.z;
    const int m0 = blockIdx.y * 64;   // i
    const int n0 = blockIdx.x * 64;   // j
    const float* Q = g_q + (size_t)b * CCH * HLN;
    const float* K = g_k + (size_t)b * CCH * HLN;

    __shared__ __align__(16) float As[16][64];
    __shared__ __align__(16) float Bs[16][64];
    float acc[4][4] = {};

    const int t  = threadIdx.x;
    const int tm = t >> 4, tn = t & 15;
    const int r  = t >> 4, c4 = (t & 15) * 4;   // 16 rows x 64 cols, natural

    for (int k0 = 0; k0 < CCH; k0 += 16) {
        *(float4*)&As[r][c4] = *(const float4*)&Q[(size_t)(k0 + r) * HLN + m0 + c4];
        *(float4*)&Bs[r][c4] = *(const float4*)&K[(size_t)(k0 + r) * HLN + n0 + c4];
        __syncthreads();
        GEMM_COMPUTE(As, Bs, acc, tm, tn)
        __syncthreads();
    }

    const float scale = 0.044194173824159216f;   // 512^-0.5
    float* S = g_s + (size_t)b * HLN * HLN;
    #pragma unroll
    for (int i = 0; i < 4; i++) {
        const size_t row = (size_t)(m0 + tm * 4 + i) * HLN + n0;
        #pragma unroll
        for (int j = 0; j < 4; j++)
            S[row + tn * 4 + j] = acc[i][j] * scale;
    }
}

// softmax over j for each (b,i) row of g_s; row is register-resident (8/thread)
__global__ void softmax_kernel() {
    const size_t row = blockIdx.x;           // b*HLN + i
    float* p = g_s + row * (size_t)HLN;
    const int t = threadIdx.x;

    float v[8];
    float m = -1e30f;
    #pragma unroll
    for (int j = 0; j < 8; j++) { v[j] = p[t + j * 256]; m = fmaxf(m, v[j]); }

    __shared__ float sh[256];
    sh[t] = m; __syncthreads();
    for (int o = 128; o > 0; o >>= 1) {
        if (t < o) sh[t] = fmaxf(sh[t], sh[t + o]);
        __syncthreads();
    }
    m = sh[0];
    __syncthreads();

    float s = 0.f;
    #pragma unroll
    for (int j = 0; j < 8; j++) { v[j] = __expf(v[j] - m); s += v[j]; }
    sh[t] = s; __syncthreads();
    for (int o = 128; o > 0; o >>= 1) {
        if (t < o) sh[t] += sh[t + o];
        __syncthreads();
    }
    const float inv = 1.f / sh[0];
    #pragma unroll
    for (int j = 0; j < 8; j++) p[t + j * 256] = v[j] * inv;
}

// v-mix: H2[b,c,i] = sum_j V[b,c,j] * P[b,i,j]
// V: [M=512, K=2048] (k contiguous) -> transpose load
// P: [N=2048, K=2048] (k contiguous) -> transpose load
__global__ void vmix_gemm() {
    const int b  = blockIdx.z;
    const int m0 = blockIdx.y * 64;   // c
    const int n0 = blockIdx.x * 64;   // i
    const float* V = g_v + (size_t)b * CCH * HLN;
    const float* P = g_s + (size_t)b * HLN * HLN;

    __shared__ __align__(16) float As[16][64];
    __shared__ __align__(16) float Bs[16][64];
    float acc[4][4] = {};

    const int t  = threadIdx.x;
    const int tm = t >> 4, tn = t & 15;
    const int r  = t >> 2, c4 = (t & 3) * 4;   // 64 rows x 16 cols, transpose

    for (int k0 = 0; k0 < HLN; k0 += 16) {
        float4 a4 = *(const float4*)&V[(size_t)(m0 + r) * HLN + k0 + c4];
        float4 b4 = *(const float4*)&P[(size_t)(n0 + r) * HLN + k0 + c4];
        As[c4 + 0][r] = a4.x; As[c4 + 1][r] = a4.y;
        As[c4 + 2][r] = a4.z; As[c4 + 3][r] = a4.w;
        Bs[c4 + 0][r] = b4.x; Bs[c4 + 1][r] = b4.y;
        Bs[c4 + 2][r] = b4.z; Bs[c4 + 3][r] = b4.w;
        __syncthreads();
        GEMM_COMPUTE(As, Bs, acc, tm, tn)
        __syncthreads();
    }

    #pragma unroll
    for (int i = 0; i < 4; i++) {
        const size_t row = (size_t)b * CCH * HLN + (size_t)(m0 + tm * 4 + i) * HLN + n0;
        #pragma unroll
        for (int j = 0; j < 4; j++)
            g_h2[row + tn * 4 + j] = acc[i][j];
    }
}

// ---------------------------------------------------------------------------
// Launch
// ---------------------------------------------------------------------------
extern "C" void kernel_launch(void* const* d_in, const int* in_sizes, int n_in,
                              void* d_out, int out_size) {
    (void)in_sizes; (void)n_in; (void)out_size;
    const float* x     = (const float*)d_in[0];
    const float* gamma = (const float*)d_in[1];
    const float* beta  = (const float*)d_in[2];
    const float* wq    = (const float*)d_in[3];
    const float* bq    = (const float*)d_in[4];
    const float* wk    = (const float*)d_in[5];
    const float* bk    = (const float*)d_in[6];
    const float* wv    = (const float*)d_in[7];
    const float* bv    = (const float*)d_in[8];
    const float* wp    = (const float*)d_in[9];
    const float* bp    = (const float*)d_in[10];
    float* out = (float*)d_out;

    float *hn, *q, *k, *v, *h2;
    cudaGetSymbolAddress((void**)&hn, g_hn);
    cudaGetSymbolAddress((void**)&q,  g_q);
    cudaGetSymbolAddress((void**)&k,  g_k);
    cudaGetSymbolAddress((void**)&v,  g_v);
    cudaGetSymbolAddress((void**)&h2, g_h2);

    dim3 conv_grid(HLN / 64, CCH / 64, BATCH);   // 32 x 8 x 8
    dim3 score_grid(HLN / 64, HLN / 64, BATCH);  // 32 x 32 x 8

    gn_kernel<<<dim3(NGRP, BATCH), 256>>>(x, gamma, beta);
    conv_gemm<false><<<conv_grid, 256>>>(wq, bq, hn, nullptr, q);
    conv_gemm<false><<<conv_grid, 256>>>(wk, bk, hn, nullptr, k);
    conv_gemm<false><<<conv_grid, 256>>>(wv, bv, hn, nullptr, v);
    score_gemm<<<score_grid, 256>>>();
    softmax_kernel<<<BATCH * HLN, 256>>>();
    vmix_gemm<<<conv_grid, 256>>>();
    conv_gemm<true><<<conv_grid, 256>>>(wp, bp, h2, x, out);
}

// round 9
// speedup vs baseline: 3.2051x; 3.2051x over previous
#include <cuda_runtime.h>
#include <cstdint>
#include <cstddef>

#define BATCH 8
#define CCH   512
#define HLN   2048
#define NGRP  32
#define CPG   16
#define EPSV  1e-6f

// ---------------------------------------------------------------------------
// Scratch (__device__ globals; alloc-free)
// ---------------------------------------------------------------------------
__device__ float g_hn[(size_t)BATCH * HLN * CCH];   // hn_t  [b][i][c]
__device__ float g_q [(size_t)BATCH * HLN * CCH];   // q_t   [b][i][c]
__device__ float g_k [(size_t)BATCH * HLN * CCH];   // k_t   [b][i][c]
__device__ float g_v [(size_t)BATCH * CCH * HLN];   // v     [b][c][j]
__device__ float g_h2[(size_t)BATCH * HLN * CCH];   // h2t   [b][i][c]
__device__ float g_s [(size_t)BATCH * HLN * HLN];   // S/P   [b][i][j]

// ---------------------------------------------------------------------------
// m16n8k8 tf32 mma (sm_80+, valid on base sm_103 target)
// ---------------------------------------------------------------------------
__device__ __forceinline__ void mma1688(float* d, const uint32_t* a, const uint32_t* b) {
    asm volatile(
        "mma.sync.aligned.m16n8k8.row.col.f32.tf32.tf32.f32 "
        "{%0,%1,%2,%3},{%4,%5,%6,%7},{%8,%9},{%0,%1,%2,%3};"
        : "+f"(d[0]), "+f"(d[1]), "+f"(d[2]), "+f"(d[3])
        : "r"(a[0]), "r"(a[1]), "r"(a[2]), "r"(a[3]), "r"(b[0]), "r"(b[1]));
}

// smem geometry (floats): row stride 36 (144B, 16B-aligned, conflict-free frags)
#define SROW   36
#define STAGEF 9216         // floats per stage: (128*36)*2 tiles
#define BOFF   4608         // B tile offset within stage (floats)
#define TPAD   132          // transpose-epilogue row stride (floats)

// ---------------------------------------------------------------------------
// cp.async tile load: 128 rows x 32 floats -> smem rows of stride SROW
// ---------------------------------------------------------------------------
__device__ __forceinline__ void ld_tile(const float* __restrict__ src, int ld,
                                        int r0, int k0, float* dstf) {
    const int t = threadIdx.x;
#pragma unroll
    for (int i = 0; i < 4; i++) {
        int ch = t + i * 256;          // 0..1023
        int r = ch >> 3, q = ch & 7;   // row, 16B quad
        const float* g = src + (size_t)(r0 + r) * ld + k0 + q * 4;
        uint32_t d;
        asm("{ .reg .u64 tt; cvta.to.shared.u64 tt, %1; cvt.u32.u64 %0, tt; }"
            : "=r"(d) : "l"(dstf + r * SROW + q * 4));
        asm volatile("cp.async.cg.shared.global [%0], [%1], 16;" :: "r"(d), "l"(g) : "memory");
    }
}

// ---------------------------------------------------------------------------
// 128x128 NT GEMM via tf32 mma.sync: D[m][n] = scale*sum_k A[m][k]*B[n][k]
//   TRANS: O[n*ldo+m] (via smem transpose); else O[m*ldo+n]
// ---------------------------------------------------------------------------
template <bool TRANS, bool BIAS, bool RESID>
__global__ void __launch_bounds__(256)
gemm_mma(const float* __restrict__ A, const float* __restrict__ B,
         float* __restrict__ O, const float* __restrict__ bias,
         const float* __restrict__ resid,
         int lda, int ldb, int ldo,
         long aB, long bB, long oB, int KT, float scale) {
    extern __shared__ float sm[];

    const int tid = threadIdx.x, wid = tid >> 5, lane = tid & 31;
    const int gI = lane >> 2, tig = lane & 3;
    const int wm = wid >> 2, wn = wid & 3;          // 2 x 4 warp grid
    const int zb = blockIdx.z;
    A += (size_t)zb * aB;
    B += (size_t)zb * bB;
    O += (size_t)zb * oB;
    const float* Rp = RESID ? resid + (size_t)zb * oB : nullptr;
    const int m0 = blockIdx.y * 128, n0 = blockIdx.x * 128;

    float acc[4][4][4];
#pragma unroll
    for (int i = 0; i < 4; i++)
#pragma unroll
        for (int j = 0; j < 4; j++)
#pragma unroll
            for (int f = 0; f < 4; f++) acc[i][j][f] = 0.f;

    const int T = KT >> 5;

    // prologue: stage 0
    ld_tile(A, lda, m0, 0, sm);
    ld_tile(B, ldb, n0, 0, sm + BOFF);
    asm volatile("cp.async.commit_group;" ::: "memory");

    for (int t = 0; t < T; t++) {
        const int cur = t & 1;
        if (t + 1 < T) {
            float* nx = sm + ((t + 1) & 1) * STAGEF;
            ld_tile(A, lda, m0, (t + 1) * 32, nx);
            ld_tile(B, ldb, n0, (t + 1) * 32, nx + BOFF);
            asm volatile("cp.async.commit_group;" ::: "memory");
            asm volatile("cp.async.wait_group 1;" ::: "memory");
        } else {
            asm volatile("cp.async.wait_group 0;" ::: "memory");
        }
        __syncthreads();

        const float* a_s = sm + cur * STAGEF;
        const float* b_s = a_s + BOFF;
#pragma unroll
        for (int ks = 0; ks < 4; ks++) {
            const int k = ks * 8;
            uint32_t af[4][4];
#pragma unroll
            for (int mi = 0; mi < 4; mi++) {
                const int r0 = wm * 64 + mi * 16 + gI;
                af[mi][0] = __float_as_uint(a_s[(r0)      * SROW + k + tig]);
                af[mi][1] = __float_as_uint(a_s[(r0 + 8)  * SROW + k + tig]);
                af[mi][2] = __float_as_uint(a_s[(r0)      * SROW + k + tig + 4]);
                af[mi][3] = __float_as_uint(a_s[(r0 + 8)  * SROW + k + tig + 4]);
            }
            uint32_t bf[4][2];
#pragma unroll
            for (int nj = 0; nj < 4; nj++) {
                const int n = wn * 32 + nj * 8 + gI;
                bf[nj][0] = __float_as_uint(b_s[n * SROW + k + tig]);
                bf[nj][1] = __float_as_uint(b_s[n * SROW + k + tig + 4]);
            }
#pragma unroll
            for (int mi = 0; mi < 4; mi++)
#pragma unroll
                for (int nj = 0; nj < 4; nj++)
                    mma1688(acc[mi][nj], af[mi], bf[nj]);
        }
        __syncthreads();   // protect smem before next-stage overwrite
    }

    // ---------------- epilogue ----------------
    if (!TRANS) {
#pragma unroll
        for (int mi = 0; mi < 4; mi++) {
#pragma unroll
            for (int h = 0; h < 2; h++) {
                const int m = m0 + wm * 64 + mi * 16 + gI + h * 8;
                float bval = BIAS ? bias[m] : 0.f;
                const size_t rowo = (size_t)m * ldo;
#pragma unroll
                for (int nj = 0; nj < 4; nj++) {
                    const int n = n0 + wn * 32 + nj * 8 + tig * 2;
                    float2 v;
                    v.x = acc[mi][nj][h * 2 + 0] * scale + bval;
                    v.y = acc[mi][nj][h * 2 + 1] * scale + bval;
                    if (RESID) {
                        float2 r = *(const float2*)&Rp[rowo + n];
                        v.x += r.x; v.y += r.y;
                    }
                    *(float2*)&O[rowo + n] = v;
                }
            }
        }
    } else {
        // smem transpose: sT[n][m], stride TPAD (conflict-free frag stores)
        float* sT = sm;
#pragma unroll
        for (int mi = 0; mi < 4; mi++) {
#pragma unroll
            for (int h = 0; h < 2; h++) {
                const int m = wm * 64 + mi * 16 + gI + h * 8;
                float bval = BIAS ? bias[m0 + m] : 0.f;
#pragma unroll
                for (int nj = 0; nj < 4; nj++) {
                    const int n = wn * 32 + nj * 8 + tig * 2;
                    sT[(n)     * TPAD + m] = acc[mi][nj][h * 2 + 0] * scale + bval;
                    sT[(n + 1) * TPAD + m] = acc[mi][nj][h * 2 + 1] * scale + bval;
                }
            }
        }
        __syncthreads();
        const int n = tid >> 1, half = tid & 1;
        const float* srow = sT + n * TPAD + half * 64;
        float* drow = O + (size_t)(n0 + n) * ldo + m0 + half * 64;
#pragma unroll
        for (int q = 0; q < 16; q++)
            *(float4*)&drow[q * 4] = *(const float4*)&srow[q * 4];
    }
}

// ---------------------------------------------------------------------------
// GroupNorm -> transposed output hn_t[b][i][c]
// ---------------------------------------------------------------------------
__global__ void gn_kernel(const float* __restrict__ x,
                          const float* __restrict__ gamma,
                          const float* __restrict__ beta) {
    const int g = blockIdx.x, b = blockIdx.y;
    const size_t base = ((size_t)b * CCH + (size_t)g * CPG) * HLN;
    const float* xp = x + base;
    const int N = CPG * HLN;
    const int tid = threadIdx.x;

    float s = 0.f, s2 = 0.f;
    for (int i = tid; i < N; i += 256) {
        float v = xp[i];
        s += v; s2 += v * v;
    }
    __shared__ float sh[256], sh2[256];
    sh[tid] = s; sh2[tid] = s2;
    __syncthreads();
    for (int o = 128; o > 0; o >>= 1) {
        if (tid < o) { sh[tid] += sh[tid + o]; sh2[tid] += sh2[tid + o]; }
        __syncthreads();
    }
    const float mean = sh[0] * (1.f / N);
    const float var  = sh2[0] * (1.f / N) - mean * mean;
    const float rstd = rsqrtf(var + EPSV);

    const int c_in = tid & 15, ir = tid >> 4;
    const float gsc = gamma[g * CPG + c_in] * rstd;
    const float gbi = beta[g * CPG + c_in] - mean * gsc;
    float* outp = g_hn + (size_t)b * HLN * CCH;

    __shared__ float tile[CPG][257];
    for (int i0 = 0; i0 < HLN; i0 += 256) {
#pragma unroll
        for (int c = 0; c < CPG; c++) tile[c][tid] = xp[c * HLN + i0 + tid];
        __syncthreads();
#pragma unroll
        for (int r = 0; r < 16; r++) {
            int ii = r * 16 + ir;
            outp[(size_t)(i0 + ii) * CCH + g * CPG + c_in] = tile[c_in][ii] * gsc + gbi;
        }
        __syncthreads();
    }
}

// ---------------------------------------------------------------------------
// Row softmax over g_s rows (length 2048)
// ---------------------------------------------------------------------------
__global__ void softmax_kernel() {
    const size_t row = blockIdx.x;
    float* p = g_s + row * (size_t)HLN;
    const int t = threadIdx.x;

    float v[8];
    float m = -1e30f;
#pragma unroll
    for (int j = 0; j < 8; j++) { v[j] = p[t + j * 256]; m = fmaxf(m, v[j]); }

    __shared__ float sh[256];
    sh[t] = m; __syncthreads();
    for (int o = 128; o > 0; o >>= 1) {
        if (t < o) sh[t] = fmaxf(sh[t], sh[t + o]);
        __syncthreads();
    }
    m = sh[0];
    __syncthreads();

    float s = 0.f;
#pragma unroll
    for (int j = 0; j < 8; j++) { v[j] = __expf(v[j] - m); s += v[j]; }
    sh[t] = s; __syncthreads();
    for (int o = 128; o > 0; o >>= 1) {
        if (t < o) sh[t] += sh[t + o];
        __syncthreads();
    }
    const float inv = 1.f / sh[0];
#pragma unroll
    for (int j = 0; j < 8; j++) p[t + j * 256] = v[j] * inv;
}

// ---------------------------------------------------------------------------
// Launch
// ---------------------------------------------------------------------------
extern "C" void kernel_launch(void* const* d_in, const int* in_sizes, int n_in,
                              void* d_out, int out_size) {
    (void)in_sizes; (void)n_in; (void)out_size;
    const float* x     = (const float*)d_in[0];
    const float* gamma = (const float*)d_in[1];
    const float* beta  = (const float*)d_in[2];
    const float* wq    = (const float*)d_in[3];
    const float* bq    = (const float*)d_in[4];
    const float* wk    = (const float*)d_in[5];
    const float* bk    = (const float*)d_in[6];
    const float* wv    = (const float*)d_in[7];
    const float* bv    = (const float*)d_in[8];
    const float* wp    = (const float*)d_in[9];
    const float* bp    = (const float*)d_in[10];
    float* out = (float*)d_out;

    float *hn, *q, *k, *v, *h2, *sbuf;
    cudaGetSymbolAddress((void**)&hn,   g_hn);
    cudaGetSymbolAddress((void**)&q,    g_q);
    cudaGetSymbolAddress((void**)&k,    g_k);
    cudaGetSymbolAddress((void**)&v,    g_v);
    cudaGetSymbolAddress((void**)&h2,   g_h2);
    cudaGetSymbolAddress((void**)&sbuf, g_s);

    const int SMEM = 2 * STAGEF * 4;   // 73728 bytes
    cudaFuncSetAttribute(gemm_mma<true,  true,  false>, cudaFuncAttributeMaxDynamicSharedMemorySize, SMEM);
    cudaFuncSetAttribute(gemm_mma<false, true,  false>, cudaFuncAttributeMaxDynamicSharedMemorySize, SMEM);
    cudaFuncSetAttribute(gemm_mma<false, false, false>, cudaFuncAttributeMaxDynamicSharedMemorySize, SMEM);
    cudaFuncSetAttribute(gemm_mma<false, true,  true >, cudaFuncAttributeMaxDynamicSharedMemorySize, SMEM);

    const long HC = (long)HLN * CCH;
    const long HH = (long)HLN * HLN;
    const float sscale = 0.044194173824159216f;   // 512^-0.5

    dim3 conv_grid(HLN / 128, CCH / 128, BATCH);   // 16 x 4 x 8
    dim3 score_grid(HLN / 128, HLN / 128, BATCH);  // 16 x 16 x 8
    dim3 vmix_grid(CCH / 128, HLN / 128, BATCH);   // 4 x 16 x 8

    gn_kernel<<<dim3(NGRP, BATCH), 256>>>(x, gamma, beta);

    // q_t = (Wq @ hn)^T   (transposed store, bias)
    gemm_mma<true, true, false><<<conv_grid, 256, SMEM>>>(
        wq, hn, q, bq, nullptr, CCH, CCH, CCH, 0, HC, HC, CCH, 1.f);
    gemm_mma<true, true, false><<<conv_grid, 256, SMEM>>>(
        wk, hn, k, bk, nullptr, CCH, CCH, CCH, 0, HC, HC, CCH, 1.f);
    // v natural [c][j]
    gemm_mma<false, true, false><<<conv_grid, 256, SMEM>>>(
        wv, hn, v, bv, nullptr, CCH, CCH, HLN, 0, HC, HC, CCH, 1.f);
    // S[i][j] = scale * q_t[i]·k_t[j]
    gemm_mma<false, false, false><<<score_grid, 256, SMEM>>>(
        q, k, sbuf, nullptr, nullptr, CCH, CCH, HLN, HC, HC, HH, CCH, sscale);
    softmax_kernel<<<BATCH * HLN, 256>>>();
    // h2t[i][c] = P[i]·V[c]   (K = 2048)
    gemm_mma<false, false, false><<<vmix_grid, 256, SMEM>>>(
        sbuf, v, h2, nullptr, nullptr, HLN, HLN, CCH, HH, HC, HC, HLN, 1.f);
    // out[o][n] = Wp[o]·h2t[n] + bp[o] + x[o][n]
    gemm_mma<false, true, true><<<conv_grid, 256, SMEM>>>(
        wp, h2, out, bp, x, CCH, CCH, HLN, 0, HC, HC, CCH, 1.f);
}

// round 14
// speedup vs baseline: 3.9899x; 1.2449x over previous
#include <cuda_runtime.h>
#include <cstdint>
#include <cstddef>

#define BATCH 8
#define CCH   512
#define HLN   2048
#define NGRP  32
#define CPG   16
#define EPSV  1e-6f

// ---------------------------------------------------------------------------
// Scratch (__device__ globals; alloc-free)
// ---------------------------------------------------------------------------
__device__ float g_hn[(size_t)BATCH * HLN * CCH];   // hn_t  [b][i][c]
__device__ float g_q [(size_t)BATCH * HLN * CCH];   // q_t   [b][i][c]
__device__ float g_k [(size_t)BATCH * HLN * CCH];   // k_t   [b][i][c]
__device__ float g_v [(size_t)BATCH * CCH * HLN];   // v     [b][c][j]
__device__ float g_h2[(size_t)BATCH * HLN * CCH];   // h2t   [b][i][c]
__device__ float g_s [(size_t)BATCH * HLN * HLN];   // S/P   [b][i][j]

// ---------------------------------------------------------------------------
// m16n8k8 tf32 mma + ldmatrix (both sm_75/80-era; valid on base sm_103)
// ---------------------------------------------------------------------------
__device__ __forceinline__ void mma1688(float* d, const uint32_t* a, const uint32_t* b) {
    asm volatile(
        "mma.sync.aligned.m16n8k8.row.col.f32.tf32.tf32.f32 "
        "{%0,%1,%2,%3},{%4,%5,%6,%7},{%8,%9},{%0,%1,%2,%3};"
        : "+f"(d[0]), "+f"(d[1]), "+f"(d[2]), "+f"(d[3])
        : "r"(a[0]), "r"(a[1]), "r"(a[2]), "r"(a[3]), "r"(b[0]), "r"(b[1]));
}
__device__ __forceinline__ void ldsm4(uint32_t* r, uint32_t addr) {
    asm volatile("ldmatrix.sync.aligned.m8n8.x4.shared.b16 {%0,%1,%2,%3}, [%4];"
                 : "=r"(r[0]), "=r"(r[1]), "=r"(r[2]), "=r"(r[3]) : "r"(addr));
}
__device__ __forceinline__ uint32_t smem_u32(const void* p) {
    uint32_t a;
    asm("{ .reg .u64 t; cvta.to.shared.u64 t, %1; cvt.u32.u64 %0, t; }"
        : "=r"(a) : "l"(p));
    return a;
}

// smem geometry (floats): row stride 36 (144B: 16B-aligned, 4-bank row stride
// -> conflict-free ldmatrix), 3 pipeline stages
#define SROW   36
#define STAGEF 9216         // floats per stage: two 128x(32..36) tiles
#define BOFF   4608         // B tile offset within stage (floats)
#define TPAD   132          // transpose-epilogue row stride (floats)

// ---------------------------------------------------------------------------
// cp.async tile load: 128 rows x 32 floats -> smem rows of stride SROW
// ---------------------------------------------------------------------------
__device__ __forceinline__ void ld_tile(const float* __restrict__ src, int ld,
                                        int r0, int k0, float* dstf) {
    const int t = threadIdx.x;
#pragma unroll
    for (int i = 0; i < 4; i++) {
        int ch = t + i * 256;          // 0..1023
        int r = ch >> 3, q = ch & 7;   // row, 16B quad
        const float* g = src + (size_t)(r0 + r) * ld + k0 + q * 4;
        uint32_t d = smem_u32(dstf + r * SROW + q * 4);
        asm volatile("cp.async.cg.shared.global [%0], [%1], 16;" :: "r"(d), "l"(g) : "memory");
    }
}

// ---------------------------------------------------------------------------
// 128x128 NT GEMM, tf32 mma.sync + ldmatrix + 3-stage cp.async ring
//   D[m][n] = scale * sum_k A[m][k]*B[n][k]
//   TRANS: O[n*ldo+m] (smem transpose); else O[m*ldo+n]
// ---------------------------------------------------------------------------
template <bool TRANS, bool BIAS, bool RESID>
__global__ void __launch_bounds__(256)
gemm_mma(const float* __restrict__ A, const float* __restrict__ B,
         float* __restrict__ O, const float* __restrict__ bias,
         const float* __restrict__ resid,
         int lda, int ldb, int ldo,
         long aB, long bB, long oB, int KT, float scale) {
    extern __shared__ float sm[];

    const int tid = threadIdx.x, wid = tid >> 5, lane = tid & 31;
    const int gI = lane >> 2, tig = lane & 3;
    const int wm = wid >> 2, wn = wid & 3;          // 2 x 4 warp grid
    const int zb = blockIdx.z;
    A += (size_t)zb * aB;
    B += (size_t)zb * bB;
    O += (size_t)zb * oB;
    const float* Rp = RESID ? resid + (size_t)zb * oB : nullptr;
    const int m0 = blockIdx.y * 128, n0 = blockIdx.x * 128;

    float acc[4][4][4];
#pragma unroll
    for (int i = 0; i < 4; i++)
#pragma unroll
        for (int j = 0; j < 4; j++)
#pragma unroll
            for (int f = 0; f < 4; f++) acc[i][j][f] = 0.f;

    // ldmatrix lane offsets (bytes within a stage)
    const int row8 = lane & 7, midx = lane >> 3;
    uint32_t aoff[4], boff[2];
#pragma unroll
    for (int mi = 0; mi < 4; mi++)
        aoff[mi] = (uint32_t)(((wm * 64 + mi * 16 + (midx & 1) * 8 + row8) * SROW
                               + (midx >> 1) * 4) * 4);
#pragma unroll
    for (int p = 0; p < 2; p++)
        boff[p] = (uint32_t)((BOFF + (wn * 32 + (2 * p + (midx >> 1)) * 8 + row8) * SROW
                              + (midx & 1) * 4) * 4);

    const uint32_t smb = smem_u32(sm);
    const int T = KT >> 5;

    // prologue: stages 0 and 1
    ld_tile(A, lda, m0, 0, sm);
    ld_tile(B, ldb, n0, 0, sm + BOFF);
    asm volatile("cp.async.commit_group;" ::: "memory");
    if (T > 1) {
        ld_tile(A, lda, m0, 32, sm + STAGEF);
        ld_tile(B, ldb, n0, 32, sm + STAGEF + BOFF);
    }
    asm volatile("cp.async.commit_group;" ::: "memory");

    int st = 0;                      // stage index t % 3
    for (int t = 0; t < T; t++) {
        asm volatile("cp.async.wait_group 1;" ::: "memory");
        __syncthreads();
        // prefetch stage t+2 (overlaps compute of stage t)
        if (t + 2 < T) {
            int s2 = st + 2; if (s2 >= 3) s2 -= 3;
            float* nx = sm + s2 * STAGEF;
            ld_tile(A, lda, m0, (t + 2) * 32, nx);
            ld_tile(B, ldb, n0, (t + 2) * 32, nx + BOFF);
        }
        asm volatile("cp.async.commit_group;" ::: "memory");

        const uint32_t stb = smb + (uint32_t)(st * STAGEF * 4);
#pragma unroll
        for (int ks = 0; ks < 4; ks++) {
            const uint32_t kb = ks * 32;   // 8 floats
            uint32_t af[4][4];
#pragma unroll
            for (int mi = 0; mi < 4; mi++) ldsm4(af[mi], stb + aoff[mi] + kb);
            uint32_t bq[2][4];
#pragma unroll
            for (int p = 0; p < 2; p++) ldsm4(bq[p], stb + boff[p] + kb);
#pragma unroll
            for (int mi = 0; mi < 4; mi++)
#pragma unroll
                for (int nj = 0; nj < 4; nj++)
                    mma1688(acc[mi][nj], af[mi], &bq[nj >> 1][(nj & 1) * 2]);
        }
        if (++st == 3) st = 0;
    }

    // ---------------- epilogue ----------------
    if (!TRANS) {
#pragma unroll
        for (int mi = 0; mi < 4; mi++) {
#pragma unroll
            for (int h = 0; h < 2; h++) {
                const int m = m0 + wm * 64 + mi * 16 + gI + h * 8;
                float bval = BIAS ? bias[m] : 0.f;
                const size_t rowo = (size_t)m * ldo;
#pragma unroll
                for (int nj = 0; nj < 4; nj++) {
                    const int n = n0 + wn * 32 + nj * 8 + tig * 2;
                    float2 v;
                    v.x = acc[mi][nj][h * 2 + 0] * scale + bval;
                    v.y = acc[mi][nj][h * 2 + 1] * scale + bval;
                    if (RESID) {
                        float2 r = *(const float2*)&Rp[rowo + n];
                        v.x += r.x; v.y += r.y;
                    }
                    *(float2*)&O[rowo + n] = v;
                }
            }
        }
    } else {
        __syncthreads();   // all warps done reading mainloop smem
        float* sT = sm;
#pragma unroll
        for (int mi = 0; mi < 4; mi++) {
#pragma unroll
            for (int h = 0; h < 2; h++) {
                const int m = wm * 64 + mi * 16 + gI + h * 8;
                float bval = BIAS ? bias[m0 + m] : 0.f;
#pragma unroll
                for (int nj = 0; nj < 4; nj++) {
                    const int n = wn * 32 + nj * 8 + tig * 2;
                    sT[(n)     * TPAD + m] = acc[mi][nj][h * 2 + 0] * scale + bval;
                    sT[(n + 1) * TPAD + m] = acc[mi][nj][h * 2 + 1] * scale + bval;
                }
            }
        }
        __syncthreads();
        const int n = tid >> 1, half = tid & 1;
        const float* srow = sT + n * TPAD + half * 64;
        float* drow = O + (size_t)(n0 + n) * ldo + m0 + half * 64;
#pragma unroll
        for (int q = 0; q < 16; q++)
            *(float4*)&drow[q * 4] = *(const float4*)&srow[q * 4];
    }
}

// ---------------------------------------------------------------------------
// GroupNorm -> transposed output hn_t[b][i][c]
// ---------------------------------------------------------------------------
__global__ void gn_kernel(const float* __restrict__ x,
                          const float* __restrict__ gamma,
                          const float* __restrict__ beta) {
    const int g = blockIdx.x, b = blockIdx.y;
    const size_t base = ((size_t)b * CCH + (size_t)g * CPG) * HLN;
    const float* xp = x + base;
    const int N = CPG * HLN;
    const int tid = threadIdx.x;

    float s = 0.f, s2 = 0.f;
    for (int i = tid; i < N; i += 256) {
        float v = xp[i];
        s += v; s2 += v * v;
    }
    __shared__ float sh[256], sh2[256];
    sh[tid] = s; sh2[tid] = s2;
    __syncthreads();
    for (int o = 128; o > 0; o >>= 1) {
        if (tid < o) { sh[tid] += sh[tid + o]; sh2[tid] += sh2[tid + o]; }
        __syncthreads();
    }
    const float mean = sh[0] * (1.f / N);
    const float var  = sh2[0] * (1.f / N) - mean * mean;
    const float rstd = rsqrtf(var + EPSV);

    const int c_in = tid & 15, ir = tid >> 4;
    const float gsc = gamma[g * CPG + c_in] * rstd;
    const float gbi = beta[g * CPG + c_in] - mean * gsc;
    float* outp = g_hn + (size_t)b * HLN * CCH;

    __shared__ float tile[CPG][257];
    for (int i0 = 0; i0 < HLN; i0 += 256) {
#pragma unroll
        for (int c = 0; c < CPG; c++) tile[c][tid] = xp[c * HLN + i0 + tid];
        __syncthreads();
#pragma unroll
        for (int r = 0; r < 16; r++) {
            int ii = r * 16 + ir;
            outp[(size_t)(i0 + ii) * CCH + g * CPG + c_in] = tile[c_in][ii] * gsc + gbi;
        }
        __syncthreads();
    }
}

// ---------------------------------------------------------------------------
// Row softmax over g_s rows (length 2048)
// ---------------------------------------------------------------------------
__global__ void softmax_kernel() {
    const size_t row = blockIdx.x;
    float* p = g_s + row * (size_t)HLN;
    const int t = threadIdx.x;

    float v[8];
    float m = -1e30f;
#pragma unroll
    for (int j = 0; j < 8; j++) { v[j] = p[t + j * 256]; m = fmaxf(m, v[j]); }

    __shared__ float sh[256];
    sh[t] = m; __syncthreads();
    for (int o = 128; o > 0; o >>= 1) {
        if (t < o) sh[t] = fmaxf(sh[t], sh[t + o]);
        __syncthreads();
    }
    m = sh[0];
    __syncthreads();

    float s = 0.f;
#pragma unroll
    for (int j = 0; j < 8; j++) { v[j] = __expf(v[j] - m); s += v[j]; }
    sh[t] = s; __syncthreads();
    for (int o = 128; o > 0; o >>= 1) {
        if (t < o) sh[t] += sh[t + o];
        __syncthreads();
    }
    const float inv = 1.f / sh[0];
#pragma unroll
    for (int j = 0; j < 8; j++) p[t + j * 256] = v[j] * inv;
}

// ---------------------------------------------------------------------------
// Launch
// ---------------------------------------------------------------------------
extern "C" void kernel_launch(void* const* d_in, const int* in_sizes, int n_in,
                              void* d_out, int out_size) {
    (void)in_sizes; (void)n_in; (void)out_size;
    const float* x     = (const float*)d_in[0];
    const float* gamma = (const float*)d_in[1];
    const float* beta  = (const float*)d_in[2];
    const float* wq    = (const float*)d_in[3];
    const float* bq    = (const float*)d_in[4];
    const float* wk    = (const float*)d_in[5];
    const float* bk    = (const float*)d_in[6];
    const float* wv    = (const float*)d_in[7];
    const float* bv    = (const float*)d_in[8];
    const float* wp    = (const float*)d_in[9];
    const float* bp    = (const float*)d_in[10];
    float* out = (float*)d_out;

    float *hn, *q, *k, *v, *h2, *sbuf;
    cudaGetSymbolAddress((void**)&hn,   g_hn);
    cudaGetSymbolAddress((void**)&q,    g_q);
    cudaGetSymbolAddress((void**)&k,    g_k);
    cudaGetSymbolAddress((void**)&v,    g_v);
    cudaGetSymbolAddress((void**)&h2,   g_h2);
    cudaGetSymbolAddress((void**)&sbuf, g_s);

    const int SMEM = 3 * STAGEF * 4;   // 110592 bytes
    cudaFuncSetAttribute(gemm_mma<true,  true,  false>, cudaFuncAttributeMaxDynamicSharedMemorySize, SMEM);
    cudaFuncSetAttribute(gemm_mma<false, true,  false>, cudaFuncAttributeMaxDynamicSharedMemorySize, SMEM);
    cudaFuncSetAttribute(gemm_mma<false, false, false>, cudaFuncAttributeMaxDynamicSharedMemorySize, SMEM);
    cudaFuncSetAttribute(gemm_mma<false, true,  true >, cudaFuncAttributeMaxDynamicSharedMemorySize, SMEM);

    const long HC = (long)HLN * CCH;
    const long HH = (long)HLN * HLN;
    const float sscale = 0.044194173824159216f;   // 512^-0.5

    dim3 conv_grid(HLN / 128, CCH / 128, BATCH);   // 16 x 4 x 8
    dim3 score_grid(HLN / 128, HLN / 128, BATCH);  // 16 x 16 x 8
    dim3 vmix_grid(CCH / 128, HLN / 128, BATCH);   // 4 x 16 x 8

    gn_kernel<<<dim3(NGRP, BATCH), 256>>>(x, gamma, beta);

    // q_t = (Wq @ hn)^T   (transposed store, bias)
    gemm_mma<true, true, false><<<conv_grid, 256, SMEM>>>(
        wq, hn, q, bq, nullptr, CCH, CCH, CCH, 0, HC, HC, CCH, 1.f);
    gemm_mma<true, true, false><<<conv_grid, 256, SMEM>>>(
        wk, hn, k, bk, nullptr, CCH, CCH, CCH, 0, HC, HC, CCH, 1.f);
    // v natural [c][j]
    gemm_mma<false, true, false><<<conv_grid, 256, SMEM>>>(
        wv, hn, v, bv, nullptr, CCH, CCH, HLN, 0, HC, HC, CCH, 1.f);
    // S[i][j] = scale * q_t[i]·k_t[j]
    gemm_mma<false, false, false><<<score_grid, 256, SMEM>>>(
        q, k, sbuf, nullptr, nullptr, CCH, CCH, HLN, HC, HC, HH, CCH, sscale);
    softmax_kernel<<<BATCH * HLN, 256>>>();
    // h2t[i][c] = P[i]·V[c]   (K = 2048)
    gemm_mma<false, false, false><<<vmix_grid, 256, SMEM>>>(
        sbuf, v, h2, nullptr, nullptr, HLN, HLN, CCH, HH, HC, HC, HLN, 1.f);
    // out[o][n] = Wp[o]·h2t[n] + bp[o] + x[o][n]
    gemm_mma<false, true, true><<<conv_grid, 256, SMEM>>>(
        wp, h2, out, bp, x, CCH, CCH, HLN, 0, HC, HC, CCH, 1.f);
}